// round 2
// baseline (speedup 1.0000x reference)
#include <cuda_runtime.h>
#include <cuda_bf16.h>
#include <math.h>

// ---------------------------------------------------------------------------
// GaussianVectorQuantizer (train path), fp32 baseline.
// Inputs (metadata order): z[8,256,4096] f32, book[1024,256] f32,
//                          log_param_q[1] f32, u[32768,1024] f32, is_train i32
// Output (flattened tuple, f32):
//   z_q[8,256,4096] | precision_q[1] | prob[32768,1024] | log_prob[32768,1024]
//   | mean_prob[1024]
// ---------------------------------------------------------------------------

static constexpr int Bb = 8;
static constexpr int Cd = 256;    // BOOK_DIM
static constexpr int Tt = 4096;
static constexpr int Nn = Bb * Tt;   // 32768 rows
static constexpr int Kb = 1024;      // BOOK_SIZE

static constexpr size_t OFF_PREC = (size_t)Bb * Cd * Tt;          // 8388608
static constexpr size_t OFF_PROB = OFF_PREC + 1;                  // odd -> scalar stores only
static constexpr size_t OFF_LOGP = OFF_PROB + (size_t)Nn * Kb;
static constexpr size_t OFF_MEAN = OFF_LOGP + (size_t)Nn * Kb;

// Scratch (device globals: no allocation allowed)
__device__ float g_zn2[Nn];
__device__ float g_ek2[Kb];
__device__ float g_enc[(size_t)Nn * Kb];   // 134 MB Gumbel-softmax encodings

// ---------------------------------------------------------------------------
// prep: book row norms, zero mean_prob, write precision_q
// ---------------------------------------------------------------------------
__global__ void prep_kernel(const float* __restrict__ book,
                            const float* __restrict__ lpq,
                            float* __restrict__ out) {
    __shared__ float red[256];
    int k = blockIdx.x, tid = threadIdx.x;
    float v = book[(size_t)k * Cd + tid];
    red[tid] = v * v;
    __syncthreads();
    for (int s = 128; s > 0; s >>= 1) {
        if (tid < s) red[tid] += red[tid + s];
        __syncthreads();
    }
    if (tid == 0) {
        g_ek2[k] = red[0];
        out[OFF_MEAN + k] = 0.0f;
        if (k == 0) out[OFF_PREC] = 0.5f / fmaxf(1.0f + expf(lpq[0]), 1e-10f);
    }
}

// ---------------------------------------------------------------------------
// z row norms: zf[n,:] = z[b, :, t], n = b*T + t. Coalesced over t.
// ---------------------------------------------------------------------------
__global__ void znorm_kernel(const float* __restrict__ z) {
    int n = blockIdx.x * blockDim.x + threadIdx.x;
    int b = n >> 12, t = n & 4095;
    const float* zp = z + (size_t)b * Cd * Tt + t;
    float acc = 0.f;
    #pragma unroll 8
    for (int c = 0; c < Cd; c++) {
        float v = zp[(size_t)c * Tt];
        acc += v * v;
    }
    g_zn2[n] = acc;
}

// ---------------------------------------------------------------------------
// GEMM1 + logits epilogue: logits[n,k] = (2*zf.book - ||z||^2 - ||e||^2)*prec
// A(m,c) = z[b, c0+c, t0+m]  (contiguous in m), B(k,c) = book[k, c]
// Tile 128x128, BK=16, 256 threads, 8x8 per-thread. Writes logits into the
// prob output region (scalar stores: region is 4-byte aligned only).
// ---------------------------------------------------------------------------
__global__ __launch_bounds__(256) void gemm1_kernel(
    const float* __restrict__ z, const float* __restrict__ book,
    const float* __restrict__ lpq, float* __restrict__ out)
{
    __shared__ float As[16][128];
    __shared__ float Bs[16][132];
    int tid = threadIdx.x;
    int tx = tid & 15, ty = tid >> 4;
    int k0 = blockIdx.x * 128;
    int m0 = blockIdx.y * 128;
    int b  = m0 >> 12;
    int t0 = m0 & 4095;
    const float* Az = z + (size_t)b * Cd * Tt + t0;

    float acc[8][8];
    #pragma unroll
    for (int i = 0; i < 8; i++)
        #pragma unroll
        for (int j = 0; j < 8; j++) acc[i][j] = 0.f;

    int lc = tid >> 5;          // 0..7   (c within A tile)
    int lm = (tid & 31) * 4;    // 0..124 (m, float4)
    int bk = tid >> 1;          // 0..127 (k row of B tile)
    int bc = (tid & 1) * 8;     // 0 or 8 (c within B tile)

    for (int kt = 0; kt < Cd / 16; kt++) {
        int c0 = kt * 16;
        float4 a0 = *(const float4*)(Az + (size_t)(c0 + lc) * Tt + lm);
        float4 a1 = *(const float4*)(Az + (size_t)(c0 + lc + 8) * Tt + lm);
        const float* Bp = book + (size_t)(k0 + bk) * Cd + c0 + bc;
        float4 b0 = *(const float4*)(Bp);
        float4 b1 = *(const float4*)(Bp + 4);
        *(float4*)&As[lc][lm]     = a0;
        *(float4*)&As[lc + 8][lm] = a1;
        Bs[bc + 0][bk] = b0.x; Bs[bc + 1][bk] = b0.y;
        Bs[bc + 2][bk] = b0.z; Bs[bc + 3][bk] = b0.w;
        Bs[bc + 4][bk] = b1.x; Bs[bc + 5][bk] = b1.y;
        Bs[bc + 6][bk] = b1.z; Bs[bc + 7][bk] = b1.w;
        __syncthreads();
        #pragma unroll
        for (int kk = 0; kk < 16; kk++) {
            float4 av0 = *(const float4*)&As[kk][ty * 8];
            float4 av1 = *(const float4*)&As[kk][ty * 8 + 4];
            float4 bv0 = *(const float4*)&Bs[kk][tx * 8];
            float4 bv1 = *(const float4*)&Bs[kk][tx * 8 + 4];
            float a[8] = {av0.x, av0.y, av0.z, av0.w, av1.x, av1.y, av1.z, av1.w};
            float c[8] = {bv0.x, bv0.y, bv0.z, bv0.w, bv1.x, bv1.y, bv1.z, bv1.w};
            #pragma unroll
            for (int i = 0; i < 8; i++)
                #pragma unroll
                for (int j = 0; j < 8; j++)
                    acc[i][j] += a[i] * c[j];
        }
        __syncthreads();
    }

    float prec = 0.5f / fmaxf(1.0f + expf(lpq[0]), 1e-10f);
    float zn[8], ek[8];
    #pragma unroll
    for (int i = 0; i < 8; i++) zn[i] = g_zn2[m0 + ty * 8 + i];
    #pragma unroll
    for (int j = 0; j < 8; j++) ek[j] = g_ek2[k0 + tx * 8 + j];
    float* L = out + OFF_PROB;
    #pragma unroll
    for (int i = 0; i < 8; i++) {
        size_t row = (size_t)(m0 + ty * 8 + i) * Kb + k0 + tx * 8;
        #pragma unroll
        for (int j = 0; j < 8; j++)
            L[row + j] = (2.f * acc[i][j] - zn[i] - ek[j]) * prec;
    }
}

// ---------------------------------------------------------------------------
// Fused softmax: prob (in-place over logits), log_prob, Gumbel encodings,
// mean_prob partial sums. One warp per row (lane owns k = i*32+lane),
// 8 warps x 4 rows per block.
// ---------------------------------------------------------------------------
__global__ __launch_bounds__(256) void softmax_kernel(
    const float* __restrict__ u, float* __restrict__ out)
{
    __shared__ float sm[8 * Kb];   // 32 KB cross-warp mean reduce
    int tid = threadIdx.x, lane = tid & 31, w = tid >> 5;
    const float invN = 1.0f / (float)Nn;

    float macc[32];
    #pragma unroll
    for (int i = 0; i < 32; i++) macc[i] = 0.f;

    for (int rr = 0; rr < 4; rr++) {
        int n = blockIdx.x * 32 + w * 4 + rr;
        float* Lrow = out + OFF_PROB + (size_t)n * Kb;      // logits (becomes prob)
        float* LPr  = out + OFF_LOGP + (size_t)n * Kb;
        const float* urow = u + (size_t)n * Kb;

        float x[32], p[32];
        float mx = -1e30f;
        #pragma unroll
        for (int i = 0; i < 32; i++) {
            x[i] = Lrow[i * 32 + lane];
            mx = fmaxf(mx, x[i]);
        }
        #pragma unroll
        for (int o = 16; o > 0; o >>= 1)
            mx = fmaxf(mx, __shfl_xor_sync(0xffffffffu, mx, o));
        float s = 0.f;
        #pragma unroll
        for (int i = 0; i < 32; i++) { p[i] = __expf(x[i] - mx); s += p[i]; }
        #pragma unroll
        for (int o = 16; o > 0; o >>= 1)
            s += __shfl_xor_sync(0xffffffffu, s, o);
        float inv = 1.f / s;
        float lZ  = logf(s);
        #pragma unroll
        for (int i = 0; i < 32; i++) {
            float pr = p[i] * inv;
            Lrow[i * 32 + lane] = pr;                 // prob
            macc[i] += pr;
            LPr[i * 32 + lane] = x[i] - mx - lZ;      // log_prob
        }

        // Gumbel-softmax encodings, temperature 0.5 (precise logf: u -> 1 edge)
        float mx2 = -1e30f;
        #pragma unroll
        for (int i = 0; i < 32; i++) {
            float uu = urow[i * 32 + lane];
            float g  = -logf(-logf(uu + 1e-10f) + 1e-10f);
            p[i] = (x[i] + g) * 2.0f;
            mx2 = fmaxf(mx2, p[i]);
        }
        #pragma unroll
        for (int o = 16; o > 0; o >>= 1)
            mx2 = fmaxf(mx2, __shfl_xor_sync(0xffffffffu, mx2, o));
        float s2 = 0.f;
        #pragma unroll
        for (int i = 0; i < 32; i++) { p[i] = __expf(p[i] - mx2); s2 += p[i]; }
        #pragma unroll
        for (int o = 16; o > 0; o >>= 1)
            s2 += __shfl_xor_sync(0xffffffffu, s2, o);
        float inv2 = 1.f / s2;
        float* Erow = g_enc + (size_t)n * Kb;
        #pragma unroll
        for (int i = 0; i < 32; i++)
            Erow[i * 32 + lane] = p[i] * inv2;
    }

    #pragma unroll
    for (int i = 0; i < 32; i++)
        sm[w * Kb + i * 32 + lane] = macc[i] * invN;
    __syncthreads();
    int k = tid * 4;
    #pragma unroll
    for (int j = 0; j < 4; j++) {
        float s = 0.f;
        #pragma unroll
        for (int ww = 0; ww < 8; ww++) s += sm[ww * Kb + k + j];
        atomicAdd(&out[OFF_MEAN + k + j], s);
    }
}

// ---------------------------------------------------------------------------
// GEMM2: z_q[n,c] = enc[n,:] . book[:,c], written transposed to [B, C, T]
// Tile 128x128, BK=16.
// ---------------------------------------------------------------------------
__global__ __launch_bounds__(256) void gemm2_kernel(
    const float* __restrict__ book, float* __restrict__ out)
{
    __shared__ float As[16][132];   // As[kk][m]
    __shared__ float Bs[16][128];   // Bs[kk][c]
    int tid = threadIdx.x;
    int tx = tid & 15, ty = tid >> 4;
    int c0 = blockIdx.x * 128;
    int m0 = blockIdx.y * 128;

    float acc[8][8];
    #pragma unroll
    for (int i = 0; i < 8; i++)
        #pragma unroll
        for (int j = 0; j < 8; j++) acc[i][j] = 0.f;

    int am = tid >> 1;          // 0..127 (m)
    int ak = (tid & 1) * 8;     // 0 or 8 (k)
    int bkk = tid >> 5;         // 0..7   (k)
    int bc4 = (tid & 31) * 4;   // c, float4

    for (int kt = 0; kt < Kb / 16; kt++) {
        int k0 = kt * 16;
        const float* Ap = g_enc + (size_t)(m0 + am) * Kb + k0 + ak;
        float4 a0 = *(const float4*)(Ap);
        float4 a1 = *(const float4*)(Ap + 4);
        float4 b0 = *(const float4*)(book + (size_t)(k0 + bkk) * Cd + c0 + bc4);
        float4 b1 = *(const float4*)(book + (size_t)(k0 + bkk + 8) * Cd + c0 + bc4);
        As[ak + 0][am] = a0.x; As[ak + 1][am] = a0.y;
        As[ak + 2][am] = a0.z; As[ak + 3][am] = a0.w;
        As[ak + 4][am] = a1.x; As[ak + 5][am] = a1.y;
        As[ak + 6][am] = a1.z; As[ak + 7][am] = a1.w;
        *(float4*)&Bs[bkk][bc4]     = b0;
        *(float4*)&Bs[bkk + 8][bc4] = b1;
        __syncthreads();
        #pragma unroll
        for (int kk = 0; kk < 16; kk++) {
            float4 av0 = *(const float4*)&As[kk][ty * 8];
            float4 av1 = *(const float4*)&As[kk][ty * 8 + 4];
            float4 bv0 = *(const float4*)&Bs[kk][tx * 8];
            float4 bv1 = *(const float4*)&Bs[kk][tx * 8 + 4];
            float a[8] = {av0.x, av0.y, av0.z, av0.w, av1.x, av1.y, av1.z, av1.w};
            float c[8] = {bv0.x, bv0.y, bv0.z, bv0.w, bv1.x, bv1.y, bv1.z, bv1.w};
            #pragma unroll
            for (int i = 0; i < 8; i++)
                #pragma unroll
                for (int j = 0; j < 8; j++)
                    acc[i][j] += a[i] * c[j];
        }
        __syncthreads();
    }

    int b = m0 >> 12;
    int t0 = (m0 & 4095) + ty * 8;
    float* Ob = out + (size_t)b * Cd * Tt;
    #pragma unroll
    for (int j = 0; j < 8; j++) {
        size_t cbase = (size_t)(c0 + tx * 8 + j) * Tt + t0;
        #pragma unroll
        for (int i = 0; i < 8; i++)
            Ob[cbase + i] = acc[i][j];
    }
}

// ---------------------------------------------------------------------------
extern "C" void kernel_launch(void* const* d_in, const int* in_sizes, int n_in,
                              void* d_out, int out_size) {
    const float* z    = (const float*)d_in[0];
    const float* book = (const float*)d_in[1];
    const float* lpq  = (const float*)d_in[2];
    const float* u    = (const float*)d_in[3];
    float* out = (float*)d_out;

    prep_kernel<<<Kb, 256>>>(book, lpq, out);
    znorm_kernel<<<Nn / 256, 256>>>(z);
    gemm1_kernel<<<dim3(Kb / 128, Nn / 128), 256>>>(z, book, lpq, out);
    softmax_kernel<<<Nn / 32, 256>>>(u, out);
    gemm2_kernel<<<dim3(Cd / 128, Nn / 128), 256>>>(book, out);
}

// round 4
// speedup vs baseline: 1.6369x; 1.6369x over previous
#include <cuda_runtime.h>
#include <cuda_bf16.h>
#include <math.h>
#include <stdint.h>

// ---------------------------------------------------------------------------
// GaussianVectorQuantizer (train path) — HMMA (mma.sync) bf16-split GEMMs.
// (tcgen05 PTX is rejected by this bench's compute_103 virtual-arch pipeline.)
// Inputs: z[8,256,4096] f32, book[1024,256] f32, log_param_q[1] f32,
//         u[32768,1024] f32, is_train i32
// Output: z_q[8,256,4096] | precision_q[1] | prob[32768,1024]
//         | log_prob[32768,1024] | mean_prob[1024]
// ---------------------------------------------------------------------------

static constexpr int Bb = 8;
static constexpr int Cd = 256;     // BOOK_DIM
static constexpr int Tt = 4096;
static constexpr int Nn = Bb * Tt; // 32768
static constexpr int Kb = 1024;    // BOOK_SIZE

static constexpr size_t OFF_PREC = (size_t)Bb * Cd * Tt;
static constexpr size_t OFF_PROB = OFF_PREC + 1;
static constexpr size_t OFF_LOGP = OFF_PROB + (size_t)Nn * Kb;
static constexpr size_t OFF_MEAN = OFF_LOGP + (size_t)Nn * Kb;

// Scratch (device globals; no allocation allowed)
__device__ float g_zn2[Nn];
__device__ float g_ek2[Kb];
__device__ __nv_bfloat16 g_zh[(size_t)Nn * Cd];   // zf hi, [n][c]
__device__ __nv_bfloat16 g_zl[(size_t)Nn * Cd];   // zf lo
__device__ __nv_bfloat16 g_bh[Kb * Cd];           // book hi, [k][c]
__device__ __nv_bfloat16 g_bl[Kb * Cd];
__device__ __nv_bfloat16 g_bth[Cd * Kb];          // book^T hi, [c][k]
__device__ __nv_bfloat16 g_btl[Cd * Kb];
__device__ __nv_bfloat16 g_eh[(size_t)Nn * Kb];   // encodings hi, [n][k]
__device__ __nv_bfloat16 g_el[(size_t)Nn * Kb];

// =============================== MMA helpers ===============================
__device__ __forceinline__ void mma16816(float c[4], const uint32_t a[4],
                                         uint32_t b0, uint32_t b1) {
    asm volatile(
        "mma.sync.aligned.m16n8k16.row.col.f32.bf16.bf16.f32 "
        "{%0,%1,%2,%3}, {%4,%5,%6,%7}, {%8,%9}, {%0,%1,%2,%3};"
        : "+f"(c[0]), "+f"(c[1]), "+f"(c[2]), "+f"(c[3])
        : "r"(a[0]), "r"(a[1]), "r"(a[2]), "r"(a[3]), "r"(b0), "r"(b1));
}

static constexpr int LDT = 40;  // smem tile stride in halves (bank-conflict-free)

// A fragment (16x16) from K-major smem tile; rows row..row+15, cols kk..kk+15
__device__ __forceinline__ void lda_frag(uint32_t a[4],
                                         const __nv_bfloat16 (*T)[LDT],
                                         int row, int kk, int g, int t2) {
    a[0] = *(const uint32_t*)&T[row + g][kk + t2];
    a[1] = *(const uint32_t*)&T[row + g + 8][kk + t2];
    a[2] = *(const uint32_t*)&T[row + g][kk + t2 + 8];
    a[3] = *(const uint32_t*)&T[row + g + 8][kk + t2 + 8];
}

// Load 128x32 bf16 tile from K-major gmem into smem (stride LDT)
__device__ __forceinline__ void load_tile(__nv_bfloat16 (*T)[LDT],
                                          const __nv_bfloat16* __restrict__ g,
                                          int ld, int kk0, int tid) {
    #pragma unroll
    for (int i = 0; i < 2; i++) {
        int idx = tid + i * 256;
        int row = idx >> 2, c8 = (idx & 3) * 8;
        *(int4*)&T[row][c8] = *(const int4*)(g + (size_t)row * ld + kk0 + c8);
    }
}

// ======================= prep: norms, book splits ==========================
__global__ void prep_kernel(const float* __restrict__ book,
                            const float* __restrict__ lpq,
                            float* __restrict__ out) {
    __shared__ float red[256];
    int k = blockIdx.x, c = threadIdx.x;
    float v = book[(size_t)k * Cd + c];
    __nv_bfloat16 hi = __float2bfloat16(v);
    __nv_bfloat16 lo = __float2bfloat16(v - __bfloat162float(hi));
    g_bh[(size_t)k * Cd + c] = hi;  g_bl[(size_t)k * Cd + c] = lo;
    g_bth[(size_t)c * Kb + k] = hi; g_btl[(size_t)c * Kb + k] = lo;
    red[c] = v * v;
    __syncthreads();
    for (int s = 128; s > 0; s >>= 1) {
        if (c < s) red[c] += red[c + s];
        __syncthreads();
    }
    if (c == 0) {
        g_ek2[k] = red[0];
        out[OFF_MEAN + k] = 0.0f;
        if (k == 0) out[OFF_PREC] = 0.5f / fmaxf(1.0f + expf(lpq[0]), 1e-10f);
    }
}

// ================= z: transpose + bf16 split  [b][c][t] -> [n][c] ==========
__global__ void zsplit_kernel(const float* __restrict__ z) {
    __shared__ float sm[32][33];
    int tx = threadIdx.x, ty = threadIdx.y;
    int t0 = blockIdx.x * 32, c0 = blockIdx.y * 32, b = blockIdx.z;
    const float* zb = z + (size_t)b * Cd * Tt;
    #pragma unroll
    for (int i = 0; i < 4; i++) {
        int cl = ty + 8 * i;
        sm[cl][tx] = zb[(size_t)(c0 + cl) * Tt + t0 + tx];
    }
    __syncthreads();
    #pragma unroll
    for (int i = 0; i < 4; i++) {
        int tl = ty + 8 * i;
        float v = sm[tx][tl];
        __nv_bfloat16 hi = __float2bfloat16(v);
        __nv_bfloat16 lo = __float2bfloat16(v - __bfloat162float(hi));
        size_t n = (size_t)b * Tt + t0 + tl;
        g_zh[n * Cd + c0 + tx] = hi;
        g_zl[n * Cd + c0 + tx] = lo;
    }
}

// =========================== z row norms ===================================
__global__ void znorm_kernel(const float* __restrict__ z) {
    int n = blockIdx.x * blockDim.x + threadIdx.x;
    int b = n >> 12, t = n & 4095;
    const float* zp = z + (size_t)b * Cd * Tt + t;
    float acc = 0.f;
    #pragma unroll 8
    for (int c = 0; c < Cd; c++) {
        float v = zp[(size_t)c * Tt];
        acc += v * v;
    }
    g_zn2[n] = acc;
}

// ================== GEMM1 (HMMA): logits = f(zf . book^T) ==================
// 128x128 tile, 8 warps in 4(m) x 2(n), BK=32, 3 split passes.
__global__ void __launch_bounds__(256) gemm1_mma(const float* __restrict__ lpq,
                                                 float* __restrict__ out) {
    __shared__ __nv_bfloat16 Ah[128][LDT], Al[128][LDT];
    __shared__ __nv_bfloat16 Bh[128][LDT], Bl[128][LDT];
    const int tid = threadIdx.x, wid = tid >> 5, lane = tid & 31;
    const int g = lane >> 2, t2 = (lane & 3) * 2;
    const int wm = (wid & 3) * 32, wn = (wid >> 2) * 64;
    const int k0 = blockIdx.x * 128;   // book rows
    const int m0 = blockIdx.y * 128;   // z rows

    float acc[2][8][4];
    #pragma unroll
    for (int i = 0; i < 2; i++)
        #pragma unroll
        for (int j = 0; j < 8; j++)
            #pragma unroll
            for (int q = 0; q < 4; q++) acc[i][j][q] = 0.f;

    for (int ch = 0; ch < Cd / 32; ch++) {
        int kk0 = ch * 32;
        load_tile(Ah, g_zh + (size_t)m0 * Cd, Cd, kk0, tid);
        load_tile(Al, g_zl + (size_t)m0 * Cd, Cd, kk0, tid);
        load_tile(Bh, g_bh + (size_t)k0 * Cd, Cd, kk0, tid);
        load_tile(Bl, g_bl + (size_t)k0 * Cd, Cd, kk0, tid);
        __syncthreads();
        #pragma unroll
        for (int ks = 0; ks < 2; ks++) {
            int kk = ks * 16;
            uint32_t ah[2][4], al[2][4];
            #pragma unroll
            for (int i = 0; i < 2; i++) {
                lda_frag(ah[i], Ah, wm + i * 16, kk, g, t2);
                lda_frag(al[i], Al, wm + i * 16, kk, g, t2);
            }
            #pragma unroll
            for (int j = 0; j < 8; j++) {
                int col = wn + j * 8 + g;
                uint32_t bh0 = *(const uint32_t*)&Bh[col][kk + t2];
                uint32_t bh1 = *(const uint32_t*)&Bh[col][kk + t2 + 8];
                uint32_t bl0 = *(const uint32_t*)&Bl[col][kk + t2];
                uint32_t bl1 = *(const uint32_t*)&Bl[col][kk + t2 + 8];
                #pragma unroll
                for (int i = 0; i < 2; i++) {
                    mma16816(acc[i][j], ah[i], bh0, bh1);
                    mma16816(acc[i][j], ah[i], bl0, bl1);
                    mma16816(acc[i][j], al[i], bh0, bh1);
                }
            }
        }
        __syncthreads();
    }

    float prec = 0.5f / fmaxf(1.0f + expf(lpq[0]), 1e-10f);
    float* L = out + OFF_PROB;
    #pragma unroll
    for (int i = 0; i < 2; i++) {
        int r0 = m0 + wm + i * 16 + g;
        float zn0 = g_zn2[r0], zn1 = g_zn2[r0 + 8];
        #pragma unroll
        for (int j = 0; j < 8; j++) {
            int c = k0 + wn + j * 8 + t2;
            float ek0 = g_ek2[c], ek1 = g_ek2[c + 1];
            L[(size_t)r0 * Kb + c]           = (2.f * acc[i][j][0] - zn0 - ek0) * prec;
            L[(size_t)r0 * Kb + c + 1]       = (2.f * acc[i][j][1] - zn0 - ek1) * prec;
            L[(size_t)(r0 + 8) * Kb + c]     = (2.f * acc[i][j][2] - zn1 - ek0) * prec;
            L[(size_t)(r0 + 8) * Kb + c + 1] = (2.f * acc[i][j][3] - zn1 - ek1) * prec;
        }
    }
}

// ========== S2: Gumbel-softmax encodings (reads logits; BEFORE S1) =========
__global__ void __launch_bounds__(256) softmax2_kernel(const float* __restrict__ u,
                                                       float* __restrict__ out) {
    int tid = threadIdx.x, lane = tid & 31, w = tid >> 5;
    for (int rr = 0; rr < 4; rr++) {
        int n = blockIdx.x * 32 + w * 4 + rr;
        const float* Lrow = out + OFF_PROB + (size_t)n * Kb;  // logits (pre-S1)
        const float* urow = u + (size_t)n * Kb;
        float x[32];
        float mx = -1e30f;
        #pragma unroll
        for (int i = 0; i < 32; i++) {
            float uu = urow[i * 32 + lane];
            float gmb = -logf(-logf(uu + 1e-10f) + 1e-10f);
            x[i] = (Lrow[i * 32 + lane] + gmb) * 2.0f;   // / TEMPERATURE(0.5)
            mx = fmaxf(mx, x[i]);
        }
        #pragma unroll
        for (int o = 16; o > 0; o >>= 1)
            mx = fmaxf(mx, __shfl_xor_sync(0xffffffffu, mx, o));
        float s = 0.f;
        #pragma unroll
        for (int i = 0; i < 32; i++) s += __expf(x[i] - mx);
        #pragma unroll
        for (int o = 16; o > 0; o >>= 1)
            s += __shfl_xor_sync(0xffffffffu, s, o);
        float inv = 1.f / s;
        __nv_bfloat16* Eh = g_eh + (size_t)n * Kb;
        __nv_bfloat16* El = g_el + (size_t)n * Kb;
        #pragma unroll
        for (int i = 0; i < 32; i++) {
            float e = __expf(x[i] - mx) * inv;
            __nv_bfloat16 hi = __float2bfloat16(e);
            Eh[i * 32 + lane] = hi;
            El[i * 32 + lane] = __float2bfloat16(e - __bfloat162float(hi));
        }
    }
}

// ===== S1: prob (in place), log_prob, mean_prob (overwrites logits) ========
__global__ void __launch_bounds__(256) softmax1_kernel(float* __restrict__ out) {
    __shared__ float sm[8 * Kb];
    int tid = threadIdx.x, lane = tid & 31, w = tid >> 5;
    for (int i = tid; i < 8 * Kb; i += 256) sm[i] = 0.f;
    __syncthreads();
    for (int rr = 0; rr < 4; rr++) {
        int n = blockIdx.x * 32 + w * 4 + rr;
        float* Lrow = out + OFF_PROB + (size_t)n * Kb;
        float* LPr  = out + OFF_LOGP + (size_t)n * Kb;
        float x[32];
        float mx = -1e30f;
        #pragma unroll
        for (int i = 0; i < 32; i++) {
            x[i] = Lrow[i * 32 + lane];
            mx = fmaxf(mx, x[i]);
        }
        #pragma unroll
        for (int o = 16; o > 0; o >>= 1)
            mx = fmaxf(mx, __shfl_xor_sync(0xffffffffu, mx, o));
        float s = 0.f;
        #pragma unroll
        for (int i = 0; i < 32; i++) s += __expf(x[i] - mx);
        #pragma unroll
        for (int o = 16; o > 0; o >>= 1)
            s += __shfl_xor_sync(0xffffffffu, s, o);
        float inv = 1.f / s;
        float lZ  = logf(s);
        #pragma unroll
        for (int i = 0; i < 32; i++) {
            float pr = __expf(x[i] - mx) * inv;
            Lrow[i * 32 + lane] = pr;
            LPr[i * 32 + lane]  = x[i] - mx - lZ;
            sm[w * Kb + i * 32 + lane] += pr;
        }
    }
    __syncthreads();
    const float invN = 1.0f / (float)Nn;
    int k = tid * 4;
    #pragma unroll
    for (int j = 0; j < 4; j++) {
        float s = 0.f;
        #pragma unroll
        for (int ww = 0; ww < 8; ww++) s += sm[ww * Kb + k + j];
        atomicAdd(&out[OFF_MEAN + k + j], s * invN);
    }
}

// ================= GEMM2 (HMMA): z_q = enc . book, -> [B,C,T] ==============
__global__ void __launch_bounds__(256) gemm2_mma(float* __restrict__ out) {
    __shared__ __nv_bfloat16 Ah[128][LDT], Al[128][LDT];
    __shared__ __nv_bfloat16 Bh[128][LDT], Bl[128][LDT];
    const int tid = threadIdx.x, wid = tid >> 5, lane = tid & 31;
    const int g = lane >> 2, t2 = (lane & 3) * 2;
    const int wm = (wid & 3) * 32, wn = (wid >> 2) * 64;
    const int c0 = blockIdx.x * 128;   // output channel
    const int m0 = blockIdx.y * 128;   // row (n)

    float acc[2][8][4];
    #pragma unroll
    for (int i = 0; i < 2; i++)
        #pragma unroll
        for (int j = 0; j < 8; j++)
            #pragma unroll
            for (int q = 0; q < 4; q++) acc[i][j][q] = 0.f;

    for (int ch = 0; ch < Kb / 32; ch++) {
        int kk0 = ch * 32;
        load_tile(Ah, g_eh + (size_t)m0 * Kb, Kb, kk0, tid);
        load_tile(Al, g_el + (size_t)m0 * Kb, Kb, kk0, tid);
        load_tile(Bh, g_bth + (size_t)c0 * Kb, Kb, kk0, tid);
        load_tile(Bl, g_btl + (size_t)c0 * Kb, Kb, kk0, tid);
        __syncthreads();
        #pragma unroll
        for (int ks = 0; ks < 2; ks++) {
            int kk = ks * 16;
            uint32_t ah[2][4], al[2][4];
            #pragma unroll
            for (int i = 0; i < 2; i++) {
                lda_frag(ah[i], Ah, wm + i * 16, kk, g, t2);
                lda_frag(al[i], Al, wm + i * 16, kk, g, t2);
            }
            #pragma unroll
            for (int j = 0; j < 8; j++) {
                int col = wn + j * 8 + g;
                uint32_t bh0 = *(const uint32_t*)&Bh[col][kk + t2];
                uint32_t bh1 = *(const uint32_t*)&Bh[col][kk + t2 + 8];
                uint32_t bl0 = *(const uint32_t*)&Bl[col][kk + t2];
                uint32_t bl1 = *(const uint32_t*)&Bl[col][kk + t2 + 8];
                #pragma unroll
                for (int i = 0; i < 2; i++) {
                    mma16816(acc[i][j], ah[i], bh0, bh1);
                    mma16816(acc[i][j], ah[i], bl0, bl1);
                    mma16816(acc[i][j], al[i], bh0, bh1);
                }
            }
        }
        __syncthreads();
    }

    int b = m0 >> 12, t0 = m0 & 4095;
    float* Ob = out + (size_t)b * Cd * Tt;
    #pragma unroll
    for (int i = 0; i < 2; i++) {
        int tp = t0 + wm + i * 16 + g;
        #pragma unroll
        for (int j = 0; j < 8; j++) {
            int c = c0 + wn + j * 8 + t2;
            Ob[(size_t)c * Tt + tp]           = acc[i][j][0];
            Ob[(size_t)(c + 1) * Tt + tp]     = acc[i][j][1];
            Ob[(size_t)c * Tt + tp + 8]       = acc[i][j][2];
            Ob[(size_t)(c + 1) * Tt + tp + 8] = acc[i][j][3];
        }
    }
}

// ---------------------------------------------------------------------------
extern "C" void kernel_launch(void* const* d_in, const int* in_sizes, int n_in,
                              void* d_out, int out_size) {
    const float* z    = (const float*)d_in[0];
    const float* book = (const float*)d_in[1];
    const float* lpq  = (const float*)d_in[2];
    const float* u    = (const float*)d_in[3];
    float* out = (float*)d_out;

    prep_kernel<<<Kb, 256>>>(book, lpq, out);
    zsplit_kernel<<<dim3(Tt / 32, Cd / 32, Bb), dim3(32, 8)>>>(z);
    znorm_kernel<<<Nn / 256, 256>>>(z);
    gemm1_mma<<<dim3(Kb / 128, Nn / 128), 256>>>(lpq, out);
    softmax2_kernel<<<Nn / 32, 256>>>(u, out);   // reads logits, writes enc
    softmax1_kernel<<<Nn / 32, 256>>>(out);      // overwrites logits with prob
    gemm2_mma<<<dim3(Cd / 128, Nn / 128), 256>>>(out);
}

// round 5
// speedup vs baseline: 1.9940x; 1.2181x over previous
#include <cuda_runtime.h>
#include <cuda_bf16.h>
#include <math.h>
#include <stdint.h>

// ---------------------------------------------------------------------------
// GaussianVectorQuantizer (train path) — HMMA bf16-split GEMMs with cp.async
// double-buffered pipelines + fused softmax.
// Inputs: z[8,256,4096] f32, book[1024,256] f32, log_param_q[1] f32,
//         u[32768,1024] f32, is_train i32
// Output: z_q[8,256,4096] | precision_q[1] | prob[32768,1024]
//         | log_prob[32768,1024] | mean_prob[1024]
// ---------------------------------------------------------------------------

static constexpr int Bb = 8;
static constexpr int Cd = 256;     // BOOK_DIM
static constexpr int Tt = 4096;
static constexpr int Nn = Bb * Tt; // 32768
static constexpr int Kb = 1024;    // BOOK_SIZE

static constexpr size_t OFF_PREC = (size_t)Bb * Cd * Tt;
static constexpr size_t OFF_PROB = OFF_PREC + 1;
static constexpr size_t OFF_LOGP = OFF_PROB + (size_t)Nn * Kb;
static constexpr size_t OFF_MEAN = OFF_LOGP + (size_t)Nn * Kb;

// Scratch (device globals; no allocation allowed)
__device__ float g_zn2[Nn];
__device__ float g_ek2[Kb];
__device__ __nv_bfloat16 g_zh[(size_t)Nn * Cd];   // zf hi, [n][c]
__device__ __nv_bfloat16 g_zl[(size_t)Nn * Cd];   // zf lo
__device__ __nv_bfloat16 g_bh[Kb * Cd];           // book hi, [k][c]
__device__ __nv_bfloat16 g_bl[Kb * Cd];
__device__ __nv_bfloat16 g_bth[Cd * Kb];          // book^T hi, [c][k]
__device__ __nv_bfloat16 g_btl[Cd * Kb];
__device__ __nv_bfloat16 g_eh[(size_t)Nn * Kb];   // encodings hi, [n][k]
__device__ __nv_bfloat16 g_el[(size_t)Nn * Kb];

// =============================== helpers ===================================
__device__ __forceinline__ uint32_t smem_u32(const void* p) {
    uint32_t a;
    asm("{ .reg .u64 t; cvta.to.shared.u64 t, %1; cvt.u32.u64 %0, t; }"
        : "=r"(a) : "l"(p));
    return a;
}
__device__ __forceinline__ void cp_async16(uint32_t saddr, const void* gptr) {
    asm volatile("cp.async.cg.shared.global [%0], [%1], 16;"
                 :: "r"(saddr), "l"(gptr));
}
__device__ __forceinline__ void cp_commit() {
    asm volatile("cp.async.commit_group;" ::: "memory");
}
template<int N> __device__ __forceinline__ void cp_wait() {
    asm volatile("cp.async.wait_group %0;" :: "n"(N) : "memory");
}
__device__ __forceinline__ void mma16816(float c[4], const uint32_t a[4],
                                         uint32_t b0, uint32_t b1) {
    asm volatile(
        "mma.sync.aligned.m16n8k16.row.col.f32.bf16.bf16.f32 "
        "{%0,%1,%2,%3}, {%4,%5,%6,%7}, {%8,%9}, {%0,%1,%2,%3};"
        : "+f"(c[0]), "+f"(c[1]), "+f"(c[2]), "+f"(c[3])
        : "r"(a[0]), "r"(a[1]), "r"(a[2]), "r"(a[3]), "r"(b0), "r"(b1));
}

static constexpr int LDT = 40;              // smem row stride in halves
static constexpr int TILE_B = 128 * LDT * 2; // 10240 bytes per 128x32 tile
static constexpr int STAGE_B = 4 * TILE_B;   // 40960 bytes per stage
static constexpr int SMEM_GEMM = 2 * STAGE_B; // 81920

// A fragment (16x16) from K-major smem tile
__device__ __forceinline__ void lda_frag(uint32_t a[4],
                                         const __nv_bfloat16 (*T)[LDT],
                                         int row, int kk, int g, int t2) {
    a[0] = *(const uint32_t*)&T[row + g][kk + t2];
    a[1] = *(const uint32_t*)&T[row + g + 8][kk + t2];
    a[2] = *(const uint32_t*)&T[row + g][kk + t2 + 8];
    a[3] = *(const uint32_t*)&T[row + g + 8][kk + t2 + 8];
}

// Async-load one 128x32 bf16 tile (K-major gmem) into smem tile at `sm`
__device__ __forceinline__ void tile_async(char* sm,
                                           const __nv_bfloat16* __restrict__ g,
                                           int ld, int kk0, int tid) {
    #pragma unroll
    for (int i = 0; i < 2; i++) {
        int idx = tid + i * 256;
        int row = idx >> 2, c8 = (idx & 3) * 8;
        cp_async16(smem_u32(sm + row * (LDT * 2) + c8 * 2),
                   g + (size_t)row * ld + kk0 + c8);
    }
}

// Pipelined 3-pass split-bf16 GEMM mainloop. NCH chunks of K=32.
template<int NCH>
__device__ __forceinline__ void gemm_body(
    const __nv_bfloat16* __restrict__ Agh, const __nv_bfloat16* __restrict__ Agl,
    const __nv_bfloat16* __restrict__ Bgh, const __nv_bfloat16* __restrict__ Bgl,
    int lda, int ldb, float acc[2][8][4], char* dsm, int tid,
    int g, int t2, int wm, int wn)
{
    auto issue = [&](int ch) {
        char* st = dsm + (ch & 1) * STAGE_B;
        int kk0 = ch * 32;
        tile_async(st + 0 * TILE_B, Agh, lda, kk0, tid);
        tile_async(st + 1 * TILE_B, Agl, lda, kk0, tid);
        tile_async(st + 2 * TILE_B, Bgh, ldb, kk0, tid);
        tile_async(st + 3 * TILE_B, Bgl, ldb, kk0, tid);
    };
    issue(0); cp_commit();
    if (NCH > 1) issue(1);
    cp_commit();

    for (int ch = 0; ch < NCH; ch++) {
        cp_wait<1>();
        __syncthreads();
        char* st = dsm + (ch & 1) * STAGE_B;
        const __nv_bfloat16 (*Ah)[LDT] = (const __nv_bfloat16 (*)[LDT])(st + 0 * TILE_B);
        const __nv_bfloat16 (*Al)[LDT] = (const __nv_bfloat16 (*)[LDT])(st + 1 * TILE_B);
        const __nv_bfloat16 (*Bh)[LDT] = (const __nv_bfloat16 (*)[LDT])(st + 2 * TILE_B);
        const __nv_bfloat16 (*Bl)[LDT] = (const __nv_bfloat16 (*)[LDT])(st + 3 * TILE_B);
        #pragma unroll
        for (int ks = 0; ks < 2; ks++) {
            int kk = ks * 16;
            uint32_t ah[2][4], al[2][4];
            #pragma unroll
            for (int i = 0; i < 2; i++) {
                lda_frag(ah[i], Ah, wm + i * 16, kk, g, t2);
                lda_frag(al[i], Al, wm + i * 16, kk, g, t2);
            }
            #pragma unroll
            for (int j = 0; j < 8; j++) {
                int col = wn + j * 8 + g;
                uint32_t bh0 = *(const uint32_t*)&Bh[col][kk + t2];
                uint32_t bh1 = *(const uint32_t*)&Bh[col][kk + t2 + 8];
                uint32_t bl0 = *(const uint32_t*)&Bl[col][kk + t2];
                uint32_t bl1 = *(const uint32_t*)&Bl[col][kk + t2 + 8];
                #pragma unroll
                for (int i = 0; i < 2; i++) {
                    mma16816(acc[i][j], ah[i], bh0, bh1);
                    mma16816(acc[i][j], ah[i], bl0, bl1);
                    mma16816(acc[i][j], al[i], bh0, bh1);
                }
            }
        }
        __syncthreads();
        if (ch + 2 < NCH) issue(ch + 2);
        cp_commit();   // always commit: uniform group accounting for cp_wait<1>
    }
}

// ======================= prep: norms, book splits ==========================
__global__ void prep_kernel(const float* __restrict__ book,
                            const float* __restrict__ lpq,
                            float* __restrict__ out) {
    __shared__ float red[256];
    int k = blockIdx.x, c = threadIdx.x;
    float v = book[(size_t)k * Cd + c];
    __nv_bfloat16 hi = __float2bfloat16(v);
    __nv_bfloat16 lo = __float2bfloat16(v - __bfloat162float(hi));
    g_bh[(size_t)k * Cd + c] = hi;  g_bl[(size_t)k * Cd + c] = lo;
    g_bth[(size_t)c * Kb + k] = hi; g_btl[(size_t)c * Kb + k] = lo;
    red[c] = v * v;
    __syncthreads();
    for (int s = 128; s > 0; s >>= 1) {
        if (c < s) red[c] += red[c + s];
        __syncthreads();
    }
    if (c == 0) {
        g_ek2[k] = red[0];
        out[OFF_MEAN + k] = 0.0f;
        if (k == 0) out[OFF_PREC] = 0.5f / fmaxf(1.0f + expf(lpq[0]), 1e-10f);
    }
}

// ================= z: transpose + bf16 split  [b][c][t] -> [n][c] ==========
__global__ void zsplit_kernel(const float* __restrict__ z) {
    __shared__ float sm[32][33];
    int tx = threadIdx.x, ty = threadIdx.y;
    int t0 = blockIdx.x * 32, c0 = blockIdx.y * 32, b = blockIdx.z;
    const float* zb = z + (size_t)b * Cd * Tt;
    #pragma unroll
    for (int i = 0; i < 4; i++) {
        int cl = ty + 8 * i;
        sm[cl][tx] = zb[(size_t)(c0 + cl) * Tt + t0 + tx];
    }
    __syncthreads();
    #pragma unroll
    for (int i = 0; i < 4; i++) {
        int tl = ty + 8 * i;
        float v = sm[tx][tl];
        __nv_bfloat16 hi = __float2bfloat16(v);
        __nv_bfloat16 lo = __float2bfloat16(v - __bfloat162float(hi));
        size_t n = (size_t)b * Tt + t0 + tl;
        g_zh[n * Cd + c0 + tx] = hi;
        g_zl[n * Cd + c0 + tx] = lo;
    }
}

// =========================== z row norms ===================================
__global__ void znorm_kernel(const float* __restrict__ z) {
    int n = blockIdx.x * blockDim.x + threadIdx.x;
    int b = n >> 12, t = n & 4095;
    const float* zp = z + (size_t)b * Cd * Tt + t;
    float acc = 0.f;
    #pragma unroll 8
    for (int c = 0; c < Cd; c++) {
        float v = zp[(size_t)c * Tt];
        acc += v * v;
    }
    g_zn2[n] = acc;
}

// ================== GEMM1 (HMMA): logits = f(zf . book^T) ==================
__global__ void __launch_bounds__(256) gemm1_mma(const float* __restrict__ lpq,
                                                 float* __restrict__ out) {
    extern __shared__ char dsm[];
    const int tid = threadIdx.x, wid = tid >> 5, lane = tid & 31;
    const int g = lane >> 2, t2 = (lane & 3) * 2;
    const int wm = (wid & 3) * 32, wn = (wid >> 2) * 64;
    const int k0 = blockIdx.x * 128;   // book rows
    const int m0 = blockIdx.y * 128;   // z rows

    float acc[2][8][4];
    #pragma unroll
    for (int i = 0; i < 2; i++)
        #pragma unroll
        for (int j = 0; j < 8; j++)
            #pragma unroll
            for (int q = 0; q < 4; q++) acc[i][j][q] = 0.f;

    gemm_body<Cd / 32>(g_zh + (size_t)m0 * Cd, g_zl + (size_t)m0 * Cd,
                       g_bh + (size_t)k0 * Cd, g_bl + (size_t)k0 * Cd,
                       Cd, Cd, acc, dsm, tid, g, t2, wm, wn);

    float prec = 0.5f / fmaxf(1.0f + expf(lpq[0]), 1e-10f);
    float* L = out + OFF_PROB;
    #pragma unroll
    for (int i = 0; i < 2; i++) {
        int r0 = m0 + wm + i * 16 + g;
        float zn0 = g_zn2[r0], zn1 = g_zn2[r0 + 8];
        #pragma unroll
        for (int j = 0; j < 8; j++) {
            int c = k0 + wn + j * 8 + t2;
            float ek0 = g_ek2[c], ek1 = g_ek2[c + 1];
            L[(size_t)r0 * Kb + c]           = (2.f * acc[i][j][0] - zn0 - ek0) * prec;
            L[(size_t)r0 * Kb + c + 1]       = (2.f * acc[i][j][1] - zn0 - ek1) * prec;
            L[(size_t)(r0 + 8) * Kb + c]     = (2.f * acc[i][j][2] - zn1 - ek0) * prec;
            L[(size_t)(r0 + 8) * Kb + c + 1] = (2.f * acc[i][j][3] - zn1 - ek1) * prec;
        }
    }
}

// ===== Fused softmax: prob/log_prob/mean (pass 1) + Gumbel enc (pass 2) ====
__global__ void __launch_bounds__(256) softmax_fused(const float* __restrict__ u,
                                                     float* __restrict__ out) {
    __shared__ float sm[8 * Kb];   // per-warp mean accumulators
    int tid = threadIdx.x, lane = tid & 31, w = tid >> 5;
    for (int i = tid; i < 8 * Kb; i += 256) sm[i] = 0.f;
    __syncthreads();

    for (int rr = 0; rr < 4; rr++) {
        int n = blockIdx.x * 32 + w * 4 + rr;
        float* Lrow = out + OFF_PROB + (size_t)n * Kb;
        float* LPr  = out + OFF_LOGP + (size_t)n * Kb;
        const float* urow = u + (size_t)n * Kb;

        float x[32];
        float mx = -1e30f;
        #pragma unroll
        for (int i = 0; i < 32; i++) {
            x[i] = Lrow[i * 32 + lane];
            mx = fmaxf(mx, x[i]);
        }
        #pragma unroll
        for (int o = 16; o > 0; o >>= 1)
            mx = fmaxf(mx, __shfl_xor_sync(0xffffffffu, mx, o));
        float s = 0.f;
        #pragma unroll
        for (int i = 0; i < 32; i++) s += __expf(x[i] - mx);
        #pragma unroll
        for (int o = 16; o > 0; o >>= 1)
            s += __shfl_xor_sync(0xffffffffu, s, o);
        float inv = 1.f / s;
        float lZ  = logf(s);
        #pragma unroll
        for (int i = 0; i < 32; i++) {
            float pr = __expf(x[i] - mx) * inv;
            Lrow[i * 32 + lane] = pr;                  // prob (in-place)
            LPr[i * 32 + lane]  = x[i] - mx - lZ;      // log_prob
            sm[w * Kb + i * 32 + lane] += pr;
        }

        // Pass 2: Gumbel-softmax encodings; overwrite x with scaled logits
        float mx2 = -1e30f;
        #pragma unroll
        for (int i = 0; i < 32; i++) {
            float uu = urow[i * 32 + lane];
            float gmb = -logf(-logf(uu + 1e-10f) + 1e-10f);
            x[i] = (x[i] + gmb) * 2.0f;   // / TEMPERATURE(0.5)
            mx2 = fmaxf(mx2, x[i]);
        }
        #pragma unroll
        for (int o = 16; o > 0; o >>= 1)
            mx2 = fmaxf(mx2, __shfl_xor_sync(0xffffffffu, mx2, o));
        float s2 = 0.f;
        #pragma unroll
        for (int i = 0; i < 32; i++) s2 += __expf(x[i] - mx2);
        #pragma unroll
        for (int o = 16; o > 0; o >>= 1)
            s2 += __shfl_xor_sync(0xffffffffu, s2, o);
        float inv2 = 1.f / s2;
        __nv_bfloat16* Eh = g_eh + (size_t)n * Kb;
        __nv_bfloat16* El = g_el + (size_t)n * Kb;
        #pragma unroll
        for (int i = 0; i < 32; i++) {
            float e = __expf(x[i] - mx2) * inv2;
            __nv_bfloat16 hi = __float2bfloat16(e);
            Eh[i * 32 + lane] = hi;
            El[i * 32 + lane] = __float2bfloat16(e - __bfloat162float(hi));
        }
    }

    __syncthreads();
    const float invN = 1.0f / (float)Nn;
    int k = tid * 4;
    #pragma unroll
    for (int j = 0; j < 4; j++) {
        float s = 0.f;
        #pragma unroll
        for (int ww = 0; ww < 8; ww++) s += sm[ww * Kb + k + j];
        atomicAdd(&out[OFF_MEAN + k + j], s * invN);
    }
}

// ================= GEMM2 (HMMA): z_q = enc . book, -> [B,C,T] ==============
__global__ void __launch_bounds__(256) gemm2_mma(float* __restrict__ out) {
    extern __shared__ char dsm[];
    const int tid = threadIdx.x, wid = tid >> 5, lane = tid & 31;
    const int g = lane >> 2, t2 = (lane & 3) * 2;
    const int wm = (wid & 3) * 32, wn = (wid >> 2) * 64;
    const int c0 = blockIdx.x * 128;   // output channel
    const int m0 = blockIdx.y * 128;   // row (n)

    float acc[2][8][4];
    #pragma unroll
    for (int i = 0; i < 2; i++)
        #pragma unroll
        for (int j = 0; j < 8; j++)
            #pragma unroll
            for (int q = 0; q < 4; q++) acc[i][j][q] = 0.f;

    gemm_body<Kb / 32>(g_eh + (size_t)m0 * Kb, g_el + (size_t)m0 * Kb,
                       g_bth + (size_t)c0 * Kb, g_btl + (size_t)c0 * Kb,
                       Kb, Kb, acc, dsm, tid, g, t2, wm, wn);

    int b = m0 >> 12, t0 = m0 & 4095;
    float* Ob = out + (size_t)b * Cd * Tt;
    #pragma unroll
    for (int i = 0; i < 2; i++) {
        int tp = t0 + wm + i * 16 + g;
        #pragma unroll
        for (int j = 0; j < 8; j++) {
            int c = c0 + wn + j * 8 + t2;
            Ob[(size_t)c * Tt + tp]           = acc[i][j][0];
            Ob[(size_t)(c + 1) * Tt + tp]     = acc[i][j][1];
            Ob[(size_t)c * Tt + tp + 8]       = acc[i][j][2];
            Ob[(size_t)(c + 1) * Tt + tp + 8] = acc[i][j][3];
        }
    }
}

// ---------------------------------------------------------------------------
extern "C" void kernel_launch(void* const* d_in, const int* in_sizes, int n_in,
                              void* d_out, int out_size) {
    const float* z    = (const float*)d_in[0];
    const float* book = (const float*)d_in[1];
    const float* lpq  = (const float*)d_in[2];
    const float* u    = (const float*)d_in[3];
    float* out = (float*)d_out;

    cudaFuncSetAttribute(gemm1_mma, cudaFuncAttributeMaxDynamicSharedMemorySize, SMEM_GEMM);
    cudaFuncSetAttribute(gemm2_mma, cudaFuncAttributeMaxDynamicSharedMemorySize, SMEM_GEMM);

    prep_kernel<<<Kb, 256>>>(book, lpq, out);
    zsplit_kernel<<<dim3(Tt / 32, Cd / 32, Bb), dim3(32, 8)>>>(z);
    znorm_kernel<<<Nn / 256, 256>>>(z);
    gemm1_mma<<<dim3(Kb / 128, Nn / 128), 256, SMEM_GEMM>>>(lpq, out);
    softmax_fused<<<Nn / 32, 256>>>(u, out);
    gemm2_mma<<<dim3(Cd / 128, Nn / 128), 256, SMEM_GEMM>>>(out);
}